// round 17
// baseline (speedup 1.0000x reference)
#include <cuda_runtime.h>
#include <cuda_bf16.h>
#include <cuda_fp16.h>
#include <cstdint>
#include <cstddef>

// ---------------------------------------------------------------------------
// Shapes: B=512, LATENT=LOCAL=256, HIDDEN=512, HW=256
// out[k][i][j] = sum_c pred[i][c] * positive[j][c][k]  - rowmax_j
// R17: contrast kernel unchanged (at legacy-HMMA floor, 148.8us measured).
//   ALL prep fused into ONE launch: blocks 0..127 run the 3-stage MLP chain
//   with grid-level barrier syncs (monotonic atomic counter, self-resetting
//   for graph replay); blocks 128..16511 run possplit concurrently.
//   Launches: 4 -> 2.
// ---------------------------------------------------------------------------

#define BSZ     512
#define LATENT  256
#define HIDDEN  512
#define HW      256
#define KP      256
#define NCHUNK  (KP / 32)        // 8

#define POS_BLOCKS 16384         // 2048 r-tiles x 8 k-tiles
#define MLP_CTAS   128

__device__ float   g_h[BSZ * HIDDEN];
__device__ float   g_a[BSZ * LATENT];
__device__ __half  g_predX[BSZ * KP];                 // 256 KB
__device__ __half  g_posX[(size_t)HW * BSZ * KP];     // 64 MB (fits in L2)
__device__ unsigned g_sync = 0;                       // MLP grid barrier

// ---------------------------------------------------------------------------
// PTX helpers (generic-target only: cp.async, ldmatrix, mma.sync)
// ---------------------------------------------------------------------------
__device__ __forceinline__ uint32_t smem_u32(const void* p) {
    uint32_t a;
    asm("{ .reg .u64 t; cvta.to.shared.u64 t, %1; cvt.u32.u64 %0, t; }"
        : "=r"(a) : "l"(p));
    return a;
}
__device__ __forceinline__ void cp16(uint32_t dst, const void* src) {
    asm volatile("cp.async.cg.shared.global [%0], [%1], 16;"
                 :: "r"(dst), "l"(src) : "memory");
}
#define CP_COMMIT() asm volatile("cp.async.commit_group;" ::: "memory")
#define CP_WAIT(N)  asm volatile("cp.async.wait_group %0;" :: "n"(N) : "memory")

__device__ __forceinline__ void ldmx4(uint32_t& r0, uint32_t& r1,
                                      uint32_t& r2, uint32_t& r3,
                                      uint32_t addr) {
    asm volatile("ldmatrix.sync.aligned.m8n8.x4.shared.b16 {%0,%1,%2,%3}, [%4];"
                 : "=r"(r0), "=r"(r1), "=r"(r2), "=r"(r3) : "r"(addr));
}
__device__ __forceinline__ void mma16816(float* c,
                                         uint32_t a0, uint32_t a1,
                                         uint32_t a2, uint32_t a3,
                                         uint32_t b0, uint32_t b1) {
    asm volatile("mma.sync.aligned.m16n8k16.row.col.f32.f16.f16.f32 "
                 "{%0,%1,%2,%3}, {%4,%5,%6,%7}, {%8,%9}, {%0,%1,%2,%3};"
                 : "+f"(c[0]), "+f"(c[1]), "+f"(c[2]), "+f"(c[3])
                 : "r"(a0), "r"(a1), "r"(a2), "r"(a3), "r"(b0), "r"(b1));
}

// SW128 over 64B logical rows: row r, quad q (16B units, q=0..3).
__device__ __forceinline__ uint32_t swz(uint32_t r, uint32_t q) {
    uint32_t R = r >> 1;
    uint32_t c = (q + ((r & 1) << 2)) ^ (R & 7);
    return R * 128 + c * 16;
}

// ---------------------------------------------------------------------------
// One 32x32 MLP GEMM tile (same accumulation order as R15/R16).
// Whole 256-thread CTA participates. smraw >= 4KB.
// ---------------------------------------------------------------------------
__device__ void gemm_tile32(const float* __restrict__ A,
                            const float* __restrict__ B,
                            const float* __restrict__ bias,
                            const float* __restrict__ res,
                            float* __restrict__ C, __half* __restrict__ Ch,
                            int N, int K, int doRelu,
                            int m0, int n0, char* smraw, int tid)
{
    float (*As)[32] = (float(*)[32])smraw;          // [16][32]
    float (*Bs)[32] = (float(*)[32])(smraw + 2048); // [16][32]
    const int tig = tid >> 4, tjg = tid & 15;

    float acc[2][2] = {};

    for (int kk = 0; kk < K; kk += 16) {
        __syncthreads();
        if (tid < 128) {                       // A: 32 rows x 4 K-quads
            const int mr = tid >> 2, q = tid & 3;
            float4 av = *(const float4*)(A + (size_t)(m0 + mr) * K + kk + q * 4);
            As[q * 4 + 0][mr] = av.x; As[q * 4 + 1][mr] = av.y;
            As[q * 4 + 2][mr] = av.z; As[q * 4 + 3][mr] = av.w;
        } else {                               // B: 16 K-rows x 8 N-quads
            const int t = tid - 128;
            const int kr = t >> 3, q = t & 7;
            float4 bv = *(const float4*)(B + (size_t)(kk + kr) * N + n0 + q * 4);
            *(float4*)&Bs[kr][q * 4] = bv;
        }
        __syncthreads();
#pragma unroll
        for (int kc = 0; kc < 16; ++kc) {
            float2 a = *(const float2*)&As[kc][tig * 2];
            float2 b = *(const float2*)&Bs[kc][tjg * 2];
            acc[0][0] = fmaf(a.x, b.x, acc[0][0]);
            acc[0][1] = fmaf(a.x, b.y, acc[0][1]);
            acc[1][0] = fmaf(a.y, b.x, acc[1][0]);
            acc[1][1] = fmaf(a.y, b.y, acc[1][1]);
        }
    }

#pragma unroll
    for (int r = 0; r < 2; ++r) {
        const int gi = m0 + tig * 2 + r;
        const int gj = n0 + tjg * 2;
        float v0 = acc[r][0], v1 = acc[r][1];
        if (bias) { v0 += bias[gj]; v1 += bias[gj + 1]; }
        if (res) {
            v0 += res[(size_t)gi * N + gj];
            v1 += res[(size_t)gi * N + gj + 1];
        }
        if (doRelu) { v0 = fmaxf(v0, 0.0f); v1 = fmaxf(v1, 0.0f); }
        if (Ch) {
            Ch[(size_t)gi * N + gj]     = __float2half(v0);
            Ch[(size_t)gi * N + gj + 1] = __float2half(v1);
        } else {
            *(float2*)&C[(size_t)gi * N + gj] = make_float2(v0, v1);
        }
    }
}

// Grid barrier among the MLP_CTAS blocks (monotonic counter, spin on >=).
__device__ __forceinline__ void mlp_barrier(int tid, unsigned target)
{
    __threadfence();          // publish this CTA's stores
    __syncthreads();
    if (tid == 0) {
        atomicAdd(&g_sync, 1u);
        while (*(volatile unsigned*)&g_sync < target) { }
        __threadfence();      // acquire
    }
    __syncthreads();
}

// ---------------------------------------------------------------------------
// Fused prep: blocks [0,128) = 3-stage MLP chain with grid syncs;
// blocks [128, 128+POS_BLOCKS) = possplit transpose+fp16.
// ---------------------------------------------------------------------------
__global__ void __launch_bounds__(256)
prep_all(const float* __restrict__ anchor, const float* __restrict__ positive,
         const float* __restrict__ W1, const float* __restrict__ b1,
         const float* __restrict__ W2, const float* __restrict__ b2,
         const float* __restrict__ Wc,
         float* __restrict__ hp, float* __restrict__ ap,
         __half* __restrict__ qx, __half* __restrict__ px)
{
    __shared__ char smraw[64 * 33 * 4];   // max(gemm 4KB, possplit 8.25KB)
    const int tid = threadIdx.x;
    const int bid = blockIdx.x;

    if (bid < MLP_CTAS) {
        // ---- stage 1: h = relu(anchor @ W1 + b1), 256 tiles (2 per CTA)
        {
            const int gBX = HIDDEN / 32;   // 16
#pragma unroll
            for (int s = 0; s < 2; ++s) {
                const int t = bid + s * MLP_CTAS;
                gemm_tile32(anchor, W1, b1, nullptr, hp, nullptr,
                            HIDDEN, LATENT, 1,
                            (t / gBX) * 32, (t % gBX) * 32, smraw, tid);
                __syncthreads();
            }
        }
        mlp_barrier(tid, MLP_CTAS);                  // counter -> 128

        // ---- stage 2: a = anchor + h @ W2 + b2, 128 tiles
        {
            const int gBX = LATENT / 32;   // 8
            gemm_tile32(hp, W2, b2, anchor, ap, nullptr,
                        LATENT, HIDDEN, 0,
                        (bid / gBX) * 32, (bid % gBX) * 32, smraw, tid);
        }
        mlp_barrier(tid, 2 * MLP_CTAS);              // counter -> 256

        // ---- stage 3: predX = fp16(a @ Wc), 128 tiles
        {
            const int gBX = LATENT / 32;   // 8
            gemm_tile32(ap, Wc, nullptr, nullptr, nullptr, qx,
                        LATENT, LATENT, 0,
                        (bid / gBX) * 32, (bid % gBX) * 32, smraw, tid);
        }
        // final arrive: 384th arrival resets the counter for the next replay
        __syncthreads();
        if (tid == 0) {
            unsigned old = atomicAdd(&g_sync, 1u);
            if (old == 3u * MLP_CTAS - 1u) atomicExch(&g_sync, 0u);
        }
    } else {
        // ---- possplit: posX[k][j][c] = fp16(positive[j][c][k]) ----
        float (*tile)[33] = (float(*)[33])smraw;     // [64][33]

        const int pb = bid - MLP_CTAS;
        const int rbase = (pb & 2047) * 64;
        const int kbase = (pb >> 11) * 32;
        const int tx = tid & 31, ty = tid >> 5;

#pragma unroll
        for (int m = 0; m < 8; ++m) {
            int r = rbase + ty + m * 8;
            tile[ty + m * 8][tx] = __ldcs(&positive[(size_t)r * 256 + kbase + tx]);
        }
        __syncthreads();

        const int kk  = tid >> 3;
        const int rr0 = (tid & 7) * 8;
        const int k   = kbase + kk;
        const int rg  = rbase + rr0;
        const int j   = rg >> 8, c = rg & 255;

        __half h[8];
#pragma unroll
        for (int e = 0; e < 8; ++e) h[e] = __float2half(tile[rr0 + e][kk]);
        *(uint4*)&px[((size_t)k * BSZ + j) * KP + c] = *(const uint4*)h;
    }
}

// ---------------------------------------------------------------------------
// HMMA contrast kernel (unchanged — measured at the legacy-HMMA floor).
// CTA = (k, 32-row i-tile), j=512, K=256. A preloaded once; 8 warp-private
// 3-stage B rings; no CTA barriers in the mainloop; prefetch before wait.
// ---------------------------------------------------------------------------
#define OF_BSL   16384                  // B slices after A region
#define CT_SMEM  (16384 + 8 * 3 * 4096) // 114688 -> 2 CTAs/SM

__global__ void __launch_bounds__(256, 2)
contrast_mma(const __half* __restrict__ predX,
             const __half* __restrict__ posX,
             float* __restrict__ out)
{
    extern __shared__ char smem[];
    const uint32_t sb = smem_u32(smem);
    const int tid = threadIdx.x;
    const int wid = tid >> 5, lid = tid & 31;
    const int k  = blockIdx.x >> 4;
    const int i0 = (blockIdx.x & 15) << 5;

    const char* Ab = (const char*)(predX + (size_t)i0 * KP);
    const char* Bw = (const char*)(posX + ((size_t)k * BSZ + wid * 64) * KP);

    float acc[16][4];   // tile t = mi*8 + njp*2 + hb
#pragma unroll
    for (int t = 0; t < 16; ++t) {
        acc[t][0] = 0.f; acc[t][1] = 0.f; acc[t][2] = 0.f; acc[t][3] = 0.f;
    }

    // ---- prologue: load ALL of A (32 rows x 256 K = 16KB, 8 chunk blocks)
    {
        const int half = tid >> 7, h = tid & 127;
        const int r = h >> 2, q = h & 3;
#pragma unroll
        for (int p = 0; p < 4; ++p) {
            const int ch = p * 2 + half;
            cp16(sb + ch * 2048 + swz(r, q),
                 Ab + (size_t)r * (KP * 2) + ch * 64 + q * 16);
        }
        CP_COMMIT();                    // group 0 (per thread): A
    }

    // ---- warp-private B loader: 64 rows x 64B per chunk into own ring ----
    const int bl_r = lid >> 2, bl_q = lid & 3;
    const uint32_t sbB = sb + OF_BSL + wid * (3 * 4096);
    auto loadB = [&](int n) {
        const uint32_t st = sbB + (n % 3) * 4096;
        const size_t co = (size_t)n * 64 + bl_q * 16;
#pragma unroll
        for (int it = 0; it < 8; ++it) {
            const int row = bl_r + it * 8;
            cp16(st + swz(row, bl_q), Bw + (size_t)row * (KP * 2) + co);
        }
        CP_COMMIT();
    };

    loadB(0);
    loadB(1);
    CP_WAIT(2);          // groups retire in order: A complete
    __syncthreads();     // A visible CTA-wide

    const uint32_t lrow = (uint32_t)(lid & 15);
    const uint32_t lqq  = (uint32_t)(lid >> 4);

#pragma unroll 1
    for (int n = 0; n < NCHUNK; ++n) {
        // issue the prefetch FIRST, then wait
        if (n + 2 < NCHUNK) { loadB(n + 2); CP_WAIT(2); }
        else if (n + 1 < NCHUNK) { CP_WAIT(1); }
        else { CP_WAIT(0); }
        __syncwarp();

        const uint32_t at = sb + n * 2048;
        const uint32_t bt = sbB + (n % 3) * 4096;

        // A fragments for this chunk (both ks halves)
        uint32_t a[2][2][4];
#pragma unroll
        for (int ks = 0; ks < 2; ++ks)
#pragma unroll
            for (int mi = 0; mi < 2; ++mi)
                ldmx4(a[ks][mi][0], a[ks][mi][1], a[ks][mi][2], a[ks][mi][3],
                      at + swz(mi * 16 + lrow, ks * 2 + lqq));

        // B fragments double-buffered across the 8 (ks,njp) steps
        uint32_t b[2][4];
        ldmx4(b[0][0], b[0][1], b[0][2], b[0][3], bt + swz(lrow, lqq));
#pragma unroll
        for (int f = 0; f < 8; ++f) {
            const int ks = f >> 2, njp = f & 3;
            if (f < 7) {
                const int g = f + 1, gks = g >> 2, gnjp = g & 3;
                ldmx4(b[g & 1][0], b[g & 1][1], b[g & 1][2], b[g & 1][3],
                      bt + swz(gnjp * 16 + lrow, gks * 2 + lqq));
            }
            const uint32_t* bb = b[f & 1];
#pragma unroll
            for (int mi = 0; mi < 2; ++mi) {
                mma16816(acc[mi * 8 + njp * 2 + 0],
                         a[ks][mi][0], a[ks][mi][1], a[ks][mi][2], a[ks][mi][3],
                         bb[0], bb[2]);
                mma16816(acc[mi * 8 + njp * 2 + 1],
                         a[ks][mi][0], a[ks][mi][1], a[ks][mi][2], a[ks][mi][3],
                         bb[1], bb[3]);
            }
        }
    }

    // ---- fused row-max: every warp covers all 32 i rows, distinct j ----
    float mx0[2], mx1[2];
#pragma unroll
    for (int mi = 0; mi < 2; ++mi) {
        mx0[mi] = -3.402823466e38f;
        mx1[mi] = -3.402823466e38f;
#pragma unroll
        for (int nj = 0; nj < 8; ++nj) {
            const float* c = acc[mi * 8 + nj];
            mx0[mi] = fmaxf(mx0[mi], fmaxf(c[0], c[1]));
            mx1[mi] = fmaxf(mx1[mi], fmaxf(c[2], c[3]));
        }
        mx0[mi] = fmaxf(mx0[mi], __shfl_xor_sync(0xffffffffu, mx0[mi], 1));
        mx0[mi] = fmaxf(mx0[mi], __shfl_xor_sync(0xffffffffu, mx0[mi], 2));
        mx1[mi] = fmaxf(mx1[mi], __shfl_xor_sync(0xffffffffu, mx1[mi], 1));
        mx1[mi] = fmaxf(mx1[mi], __shfl_xor_sync(0xffffffffu, mx1[mi], 2));
    }

    __syncthreads();                 // ALL warps done with mainloop SMEM
    float* rmax = (float*)smem;      // reuse A region: [8 warps][32 rows]
    const int tr = lid >> 2;         // 0..7
    if ((lid & 3) == 0) {
#pragma unroll
        for (int mi = 0; mi < 2; ++mi) {
            rmax[wid * 32 + mi * 16 + tr]     = mx0[mi];
            rmax[wid * 32 + mi * 16 + 8 + tr] = mx1[mi];
        }
    }
    __syncthreads();

    float m0[2], m1[2];
#pragma unroll
    for (int mi = 0; mi < 2; ++mi) {
        float a0 = -3.402823466e38f, a1 = -3.402823466e38f;
#pragma unroll
        for (int w = 0; w < 8; ++w) {
            a0 = fmaxf(a0, rmax[w * 32 + mi * 16 + tr]);
            a1 = fmaxf(a1, rmax[w * 32 + mi * 16 + 8 + tr]);
        }
        m0[mi] = a0; m1[mi] = a1;
    }

    // ---- subtract + streaming store (evict-first: keep posX resident) ----
    const size_t obase = ((size_t)k * BSZ + i0) * BSZ + wid * 64 + (lid & 3) * 2;
#pragma unroll
    for (int mi = 0; mi < 2; ++mi) {
        float* o0 = out + obase + (size_t)(mi * 16 + tr) * BSZ;
        float* o1 = o0 + (size_t)8 * BSZ;
#pragma unroll
        for (int nj = 0; nj < 8; ++nj) {
            const float* c = acc[mi * 8 + nj];
            __stcs((float2*)(o0 + nj * 8), make_float2(c[0] - m0[mi], c[1] - m0[mi]));
            __stcs((float2*)(o1 + nj * 8), make_float2(c[2] - m1[mi], c[3] - m1[mi]));
        }
    }
}

// ---------------------------------------------------------------------------
// Launch
// ---------------------------------------------------------------------------
extern "C" void kernel_launch(void* const* d_in, const int* in_sizes, int n_in,
                              void* d_out, int out_size)
{
    const float* anchor   = (const float*)d_in[0];
    const float* positive = (const float*)d_in[1];
    const float* W1       = (const float*)d_in[2];
    const float* b1       = (const float*)d_in[3];
    const float* W2       = (const float*)d_in[4];
    const float* b2       = (const float*)d_in[5];
    const float* Wc       = (const float*)d_in[6];
    float* out            = (float*)d_out;

    float *hp, *ap;
    __half *px, *qx;
    cudaGetSymbolAddress((void**)&hp, g_h);
    cudaGetSymbolAddress((void**)&ap, g_a);
    cudaGetSymbolAddress((void**)&qx, g_predX);
    cudaGetSymbolAddress((void**)&px, g_posX);

    cudaFuncSetAttribute(contrast_mma,
                         cudaFuncAttributeMaxDynamicSharedMemorySize, CT_SMEM);

    // ONE fused prep launch: MLP chain (blocks 0..127, grid-synced) +
    // possplit (blocks 128..16511)
    prep_all<<<MLP_CTAS + POS_BLOCKS, 256>>>(
        anchor, positive, W1, b1, W2, b2, Wc, hp, ap, qx, px);

    // HMMA contrast GEMM + fused rowmax (2 CTAs/SM, barrier-free mainloop)
    contrast_mma<<<HW * 16, 256, CT_SMEM>>>(qx, px, out);
}